// round 3
// baseline (speedup 1.0000x reference)
#include <cuda_runtime.h>

typedef unsigned long long u64;

#define TPB 128
#define RPT 3                 // rows per thread
#define RPC (TPB * RPT)       // rows per CTA = 384
#define NXC 64
#define NQC 64
#define NUC 16
#define PAD 68                // padded SMEM column stride (floats), 16B-aligned

#define N_MAX 262144
__device__ float w_scratch[(size_t)(N_MAX + RPC) * NQC];

// SMEM floats: 3*(64*68) + 2*(16*68) + 64*64 + 64 + 64 = 19456 -> 76KB
#define SMEM_FLOATS (3*(NXC*PAD) + 2*(NUC*PAD) + NQC*NQC + NQC + NXC)
#define SMEM_BYTES (SMEM_FLOATS * 4)

#define FMA2(d, a, b) asm("fma.rn.f32x2 %0, %1, %2, %0;" : "+l"(d) : "l"(a), "l"(b))
#define DUP(d, f)     asm("mov.b64 %0, {%1, %1};" : "=l"(d) : "f"(f))
#define UNPK(lo, hi, v) asm("mov.b64 {%0, %1}, %2;" : "=f"(lo), "=f"(hi) : "l"(v))
#define PK(d, lo, hi)   asm("mov.b64 %0, {%1, %2};" : "=l"(d) : "f"(lo), "f"(hi))

// Accumulate one weight column (64 floats = 32 packed pairs) into 3 rows' accumulators
// with per-row duplicated scalar multipliers m0/m1/m2.
#define ACC_COL(A0, A1, A2, COLP, M0, M1, M2) do {                          \
    const ulonglong2* _c = (const ulonglong2*)(COLP);                       \
    _Pragma("unroll")                                                       \
    for (int _pp = 0; _pp < 16; ++_pp) {                                    \
        ulonglong2 _q = _c[_pp];                                            \
        FMA2(A0[2*_pp],   _q.x, M0); FMA2(A0[2*_pp+1], _q.y, M0);           \
        FMA2(A1[2*_pp],   _q.x, M1); FMA2(A1[2*_pp+1], _q.y, M1);           \
        FMA2(A2[2*_pp],   _q.x, M2); FMA2(A2[2*_pp+1], _q.y, M2);           \
    }                                                                       \
} while (0)

// Stream a multiplier section (CNT4 float4-chunks) from 3 global row pointers,
// accumulating against transposed-weight columns at WBASE (stride PAD).
#define STREAM_SECTION(A0, A1, A2, WBASE, P0, P1, P2, CNT4, V2) do {        \
    for (int _j4 = 0; _j4 < (CNT4); ++_j4) {                                \
        float4 _f0 = *(const float4*)((P0) + 4*_j4);                        \
        float4 _f1 = *(const float4*)((P1) + 4*_j4);                        \
        float4 _f2 = (V2) ? *(const float4*)((P2) + 4*_j4)                  \
                          : make_float4(0.f,0.f,0.f,0.f);                   \
        _Pragma("unroll")                                                   \
        for (int _jj = 0; _jj < 4; ++_jj) {                                 \
            float _s0 = _jj==0?_f0.x:_jj==1?_f0.y:_jj==2?_f0.z:_f0.w;       \
            float _s1 = _jj==0?_f1.x:_jj==1?_f1.y:_jj==2?_f1.z:_f1.w;       \
            float _s2 = _jj==0?_f2.x:_jj==1?_f2.y:_jj==2?_f2.z:_f2.w;       \
            u64 _m0, _m1, _m2;                                              \
            DUP(_m0, _s0); DUP(_m1, _s1); DUP(_m2, _s2);                    \
            const float* _col = (WBASE) + (4*_j4 + _jj) * PAD;              \
            ACC_COL(A0, A1, A2, _col, _m0, _m1, _m2);                       \
        }                                                                   \
    }                                                                       \
} while (0)

__global__ __launch_bounds__(TPB, 2)
void ren_fused_kernel(const float* __restrict__ x, const float* __restrict__ u,
                      const float* __restrict__ A, const float* __restrict__ B1,
                      const float* __restrict__ B2, const float* __restrict__ C1,
                      const float* __restrict__ D11, const float* __restrict__ D12,
                      const float* __restrict__ bv, const float* __restrict__ bx,
                      float* __restrict__ out, int n) {
    extern __shared__ float sm[];
    float* sC1t  = sm;                    // [j: 64][i: 64] stride PAD
    float* sAt   = sC1t  + NXC * PAD;     // [j: 64][k: 64]
    float* sB1t  = sAt   + NXC * PAD;     // [j: 64][k: 64]
    float* sD12t = sB1t  + NXC * PAD;     // [j: 16][i: 64]
    float* sB2t  = sD12t + NUC * PAD;     // [j: 16][k: 64]
    float* sD11  = sB2t  + NUC * PAD;     // natural row-major [i][j]
    float* sbv   = sD11  + NQC * NQC;
    float* sbx   = sbv   + NQC;

    // ---- load weights (square matrices transposed into padded layout) ----
    for (int idx = threadIdx.x; idx < NXC * NXC; idx += TPB) {
        int i = idx >> 6, j = idx & 63;
        sC1t[j * PAD + i] = C1[idx];
        sAt [j * PAD + i] = A[idx];
        sB1t[j * PAD + i] = B1[idx];
        sD11[idx] = D11[idx];
    }
    for (int idx = threadIdx.x; idx < NXC * NUC; idx += TPB) {
        int i = idx >> 4, j = idx & 15;
        sD12t[j * PAD + i] = D12[idx];
        sB2t [j * PAD + i] = B2[idx];
    }
    if (threadIdx.x < NQC) {
        sbv[threadIdx.x] = bv[threadIdx.x];
        sbx[threadIdx.x] = bx[threadIdx.x];
    }
    __syncthreads();

    const int t = threadIdx.x;
    const size_t r0 = (size_t)blockIdx.x * RPC + t;
    const size_t r1 = r0 + TPB;
    const size_t r2 = r0 + 2 * TPB;
    if (r0 >= (size_t)n) return;               // whole tail threads (never for 262144)
    const bool v1 = r1 < (size_t)n;
    const bool v2 = r2 < (size_t)n;
    const size_t r1s = v1 ? r1 : r0;           // safe aliases for loads
    const size_t r2s = v2 ? r2 : r0;

    // =====================================================================
    // Stage 1: base = C1 x + D12 u + bv   (accumulator-resident, packed pairs)
    // =====================================================================
    u64 bp0[32], bp1[32], bp2[32];
    {
        const u64* bvp = (const u64*)sbv;
        #pragma unroll
        for (int p = 0; p < 32; ++p) { u64 b = bvp[p]; bp0[p] = b; bp1[p] = b; bp2[p] = b; }
    }
    STREAM_SECTION(bp0, bp1, bp2, sC1t,  x + r0*NXC, x + r1s*NXC, x + r2s*NXC, NXC/4, true);
    STREAM_SECTION(bp0, bp1, bp2, sD12t, u + r0*NUC, u + r1s*NUC, u + r2s*NUC, NUC/4, true);

    // =====================================================================
    // Stage 2: forward substitution w = relu(base + D11 w), in place on bp*.
    // bp[p] holds (base[2p], base[2p+1]) until step 2p+1 completes, then (w[2p], w[2p+1]).
    // =====================================================================
    float wprev0 = 0.f, wprev1 = 0.f, wprev2 = 0.f;
    float bh0 = 0.f, bh1 = 0.f, bh2 = 0.f;
    #pragma unroll
    for (int i = 0; i < NQC; ++i) {
        const int p = i >> 1;
        const float* d11r = sD11 + i * NQC;
        u64 s00 = 0ull, s01 = 0ull, s10 = 0ull, s11 = 0ull, s20 = 0ull, s21 = 0ull;
        const ulonglong2* dr = (const ulonglong2*)d11r;
        #pragma unroll
        for (int qq = 0; qq < (p >> 1); ++qq) {          // pairs-of-pairs below diagonal
            ulonglong2 q = dr[qq];
            FMA2(s00, q.x, bp0[2*qq]); FMA2(s01, q.y, bp0[2*qq+1]);
            FMA2(s10, q.x, bp1[2*qq]); FMA2(s11, q.y, bp1[2*qq+1]);
            FMA2(s20, q.x, bp2[2*qq]); FMA2(s21, q.y, bp2[2*qq+1]);
        }
        if (p & 1) {                                     // leftover full pair
            u64 q = ((const u64*)d11r)[p - 1];
            FMA2(s00, q, bp0[p-1]); FMA2(s10, q, bp1[p-1]); FMA2(s20, q, bp2[p-1]);
        }
        float base0, base1, base2;
        if (!(i & 1)) {                                  // even: unpack pair, save hi
            UNPK(base0, bh0, bp0[p]); UNPK(base1, bh1, bp1[p]); UNPK(base2, bh2, bp2[p]);
        } else { base0 = bh0; base1 = bh1; base2 = bh2; }

        float va, vb, vc, vd, v0, v1c, v2c;
        UNPK(va, vb, s00); UNPK(vc, vd, s01); v0  = base0 + ((va+vb)+(vc+vd));
        UNPK(va, vb, s10); UNPK(vc, vd, s11); v1c = base1 + ((va+vb)+(vc+vd));
        UNPK(va, vb, s20); UNPK(vc, vd, s21); v2c = base2 + ((va+vb)+(vc+vd));
        if (i & 1) {                                     // odd: scalar term w[i-1]
            float dlast = d11r[i - 1];
            v0  = fmaf(dlast, wprev0, v0);
            v1c = fmaf(dlast, wprev1, v1c);
            v2c = fmaf(dlast, wprev2, v2c);
        }
        v0 = fmaxf(v0, 0.f); v1c = fmaxf(v1c, 0.f); v2c = fmaxf(v2c, 0.f);
        if (i & 1) { PK(bp0[p], wprev0, v0); PK(bp1[p], wprev1, v1c); PK(bp2[p], wprev2, v2c); }
        else       { wprev0 = v0; wprev1 = v1c; wprev2 = v2c; }
    }

    // spill w to global scratch (same thread rereads it in stage 3)
    {
        ulonglong2* w0 = (ulonglong2*)(w_scratch + r0 * NQC);
        ulonglong2* w1 = (ulonglong2*)(w_scratch + r1 * NQC);
        ulonglong2* w2p = (ulonglong2*)(w_scratch + r2 * NQC);
        #pragma unroll
        for (int q = 0; q < 16; ++q) {
            ulonglong2 t2;
            t2.x = bp0[2*q]; t2.y = bp0[2*q+1]; w0[q] = t2;
            if (v1) { t2.x = bp1[2*q]; t2.y = bp1[2*q+1]; w1[q] = t2; }
            if (v2) { t2.x = bp2[2*q]; t2.y = bp2[2*q+1]; w2p[q] = t2; }
        }
    }

    // =====================================================================
    // Stage 3: out = A x + B1 w + B2 u + bx   (accumulator-resident)
    // bp* registers are dead here; oa* takes their place.
    // =====================================================================
    u64 oa0[32], oa1[32], oa2[32];
    {
        const u64* bxp = (const u64*)sbx;
        #pragma unroll
        for (int p = 0; p < 32; ++p) { u64 b = bxp[p]; oa0[p] = b; oa1[p] = b; oa2[p] = b; }
    }
    STREAM_SECTION(oa0, oa1, oa2, sAt,  x + r0*NXC, x + r1s*NXC, x + r2s*NXC, NXC/4, true);
    STREAM_SECTION(oa0, oa1, oa2, sB1t,
                   w_scratch + r0*NQC, w_scratch + r1s*NQC, w_scratch + r2s*NQC, NQC/4, true);
    STREAM_SECTION(oa0, oa1, oa2, sB2t, u + r0*NUC, u + r1s*NUC, u + r2s*NUC, NUC/4, true);

    {
        ulonglong2* o0 = (ulonglong2*)(out + r0 * NXC);
        ulonglong2* o1 = (ulonglong2*)(out + r1 * NXC);
        ulonglong2* o2 = (ulonglong2*)(out + r2 * NXC);
        #pragma unroll
        for (int q = 0; q < 16; ++q) {
            ulonglong2 t2;
            t2.x = oa0[2*q]; t2.y = oa0[2*q+1]; o0[q] = t2;
            if (v1) { t2.x = oa1[2*q]; t2.y = oa1[2*q+1]; o1[q] = t2; }
            if (v2) { t2.x = oa2[2*q]; t2.y = oa2[2*q+1]; o2[q] = t2; }
        }
    }
}

extern "C" void kernel_launch(void* const* d_in, const int* in_sizes, int n_in,
                              void* d_out, int out_size) {
    const float* x   = (const float*)d_in[0];
    const float* u   = (const float*)d_in[1];
    const float* A   = (const float*)d_in[2];
    const float* B1  = (const float*)d_in[3];
    const float* B2  = (const float*)d_in[4];
    const float* C1  = (const float*)d_in[5];
    const float* D11 = (const float*)d_in[6];
    const float* D12 = (const float*)d_in[7];
    const float* bv  = (const float*)d_in[8];
    const float* bx  = (const float*)d_in[9];
    float* out = (float*)d_out;

    const int n = in_sizes[0] / NXC;   // 262144 rows
    cudaFuncSetAttribute(ren_fused_kernel,
                         cudaFuncAttributeMaxDynamicSharedMemorySize, SMEM_BYTES);
    const int blocks = (n + RPC - 1) / RPC;
    ren_fused_kernel<<<blocks, TPB, SMEM_BYTES>>>(x, u, A, B1, B2, C1, D11, D12,
                                                  bv, bx, out, n);
}

// round 4
// speedup vs baseline: 1.3815x; 1.3815x over previous
#include <cuda_runtime.h>

typedef unsigned long long u64;

#define TPB 256
#define RPT 2
#define RPC (TPB * RPT)       // 512 rows per CTA
#define NXC 64
#define NQC 64
#define NUC 16
#define PAD 68                // padded column stride (floats)

#define N_MAX 262144
// w scratch, slot-interleaved: w2[slot * TOT + gtid], 64 u64 slots per thread
__device__ u64 w_scratch_u64[64ULL * (N_MAX / 2 + 256)];

// SMEM: C1t(64*68) At(64*68) B1t(64*68) D12t(16*68) B2t(16*68) D11(64*64) bv(64) bx(64)
#define SMEM_FLOATS (3*(NXC*PAD) + 2*(NUC*PAD) + NQC*NQC + NQC + NXC)
#define SMEM_BYTES (SMEM_FLOATS * 4)

#define FMA2(d, a, b)  asm("fma.rn.f32x2 %0, %1, %2, %0;" : "+l"(d) : "l"(a), "l"(b))
#define DUP(d, f)      asm("mov.b64 %0, {%1, %1};" : "=l"(d) : "f"(f))
#define UNPK(lo, hi, v) asm("mov.b64 {%0, %1}, %2;" : "=f"(lo), "=f"(hi) : "l"(v))
#define PK(d, lo, hi)   asm("mov.b64 %0, {%1, %2};" : "=l"(d) : "f"(lo), "f"(hi))

// One transposed-weight column (64 floats) into both rows' 32-pair accumulators.
__device__ __forceinline__ void acc_col(u64* a0, u64* a1, const float* col,
                                        u64 m0, u64 m1) {
    const ulonglong2* c = (const ulonglong2*)col;
    #pragma unroll
    for (int pp = 0; pp < 16; ++pp) {
        ulonglong2 q = c[pp];
        FMA2(a0[2*pp],   q.x, m0); FMA2(a0[2*pp+1], q.y, m0);
        FMA2(a1[2*pp],   q.x, m1); FMA2(a1[2*pp+1], q.y, m1);
    }
}

// Stream CNT4 float4-chunks of multipliers from two global row pointers against
// transposed weights (stride PAD).
template <int CNT4>
__device__ __forceinline__ void stream_sec(u64* a0, u64* a1, const float* wt,
                                           const float* p0, const float* p1) {
    #pragma unroll 1
    for (int j4 = 0; j4 < CNT4; ++j4) {
        float4 f0 = *(const float4*)(p0 + 4*j4);
        float4 f1 = *(const float4*)(p1 + 4*j4);
        const float* col = wt + 4*j4*PAD;
        u64 m0, m1;
        DUP(m0, f0.x); DUP(m1, f1.x); acc_col(a0, a1, col,          m0, m1);
        DUP(m0, f0.y); DUP(m1, f1.y); acc_col(a0, a1, col + PAD,    m0, m1);
        DUP(m0, f0.z); DUP(m1, f1.z); acc_col(a0, a1, col + 2*PAD,  m0, m1);
        DUP(m0, f0.w); DUP(m1, f1.w); acc_col(a0, a1, col + 3*PAD,  m0, m1);
    }
}

__global__ __launch_bounds__(TPB, 1)
void ren_fused_kernel(const float* __restrict__ x, const float* __restrict__ u,
                      const float* __restrict__ A, const float* __restrict__ B1,
                      const float* __restrict__ B2, const float* __restrict__ C1,
                      const float* __restrict__ D11, const float* __restrict__ D12,
                      const float* __restrict__ bv, const float* __restrict__ bx,
                      float* __restrict__ out, int n) {
    extern __shared__ float sm[];
    float* sC1t  = sm;                    // [j][i] stride PAD
    float* sAt   = sC1t  + NXC * PAD;
    float* sB1t  = sAt   + NXC * PAD;
    float* sD12t = sB1t  + NXC * PAD;     // [j:16][i] stride PAD
    float* sB2t  = sD12t + NUC * PAD;
    float* sD11  = sB2t  + NUC * PAD;     // row-major
    float* sbv   = sD11  + NQC * NQC;
    float* sbx   = sbv   + NQC;

    for (int idx = threadIdx.x; idx < NXC * NXC; idx += TPB) {
        int i = idx >> 6, j = idx & 63;
        sC1t[j * PAD + i] = C1[idx];
        sAt [j * PAD + i] = A[idx];
        sB1t[j * PAD + i] = B1[idx];
        sD11[idx] = D11[idx];
    }
    for (int idx = threadIdx.x; idx < NXC * NUC; idx += TPB) {
        int i = idx >> 4, j = idx & 15;
        sD12t[j * PAD + i] = D12[idx];
        sB2t [j * PAD + i] = B2[idx];
    }
    if (threadIdx.x < NQC) {
        sbv[threadIdx.x] = bv[threadIdx.x];
        sbx[threadIdx.x] = bx[threadIdx.x];
    }
    __syncthreads();

    const int t = threadIdx.x;
    const size_t r0 = (size_t)blockIdx.x * RPC + t;
    const size_t r1 = r0 + TPB;
    if (r0 >= (size_t)n) return;
    const bool v1 = r1 < (size_t)n;
    const size_t r1s = v1 ? r1 : r0;
    const size_t gt  = (size_t)blockIdx.x * TPB + t;      // global thread id
    const size_t TOT = (size_t)gridDim.x * TPB;           // slot stride

    // ================= Stage 1: base = C1 x + D12 u + bv =================
    u64 bp0[32], bp1[32];
    {
        const u64* bvp = (const u64*)sbv;
        #pragma unroll
        for (int p = 0; p < 32; ++p) { u64 b = bvp[p]; bp0[p] = b; bp1[p] = b; }
    }
    stream_sec<NXC/4>(bp0, bp1, sC1t,  x + r0*NXC, x + r1s*NXC);
    stream_sec<NUC/4>(bp0, bp1, sD12t, u + r0*NUC, u + r1s*NUC);

    // ============ Stage 2: w = relu(base + D11 w), in place on bp ============
    {
        float wprev0 = 0.f, wprev1 = 0.f, bh0 = 0.f, bh1 = 0.f;
        #pragma unroll
        for (int i = 0; i < NQC; ++i) {
            const int p = i >> 1;
            const float* d11r = sD11 + i * NQC;
            u64 s00 = 0ull, s01 = 0ull, s10 = 0ull, s11 = 0ull;
            const ulonglong2* dr = (const ulonglong2*)d11r;
            #pragma unroll
            for (int qq = 0; qq < (p >> 1); ++qq) {
                ulonglong2 q = dr[qq];
                FMA2(s00, q.x, bp0[2*qq]); FMA2(s01, q.y, bp0[2*qq+1]);
                FMA2(s10, q.x, bp1[2*qq]); FMA2(s11, q.y, bp1[2*qq+1]);
            }
            if (p & 1) {
                u64 q = ((const u64*)d11r)[p - 1];
                FMA2(s00, q, bp0[p-1]); FMA2(s10, q, bp1[p-1]);
            }
            float base0, base1;
            if (!(i & 1)) { UNPK(base0, bh0, bp0[p]); UNPK(base1, bh1, bp1[p]); }
            else          { base0 = bh0; base1 = bh1; }

            float va, vb, vc, vd, v0, v1c;
            UNPK(va, vb, s00); UNPK(vc, vd, s01); v0  = base0 + ((va+vb)+(vc+vd));
            UNPK(va, vb, s10); UNPK(vc, vd, s11); v1c = base1 + ((va+vb)+(vc+vd));
            if (i & 1) {
                float dl = d11r[i - 1];
                v0  = fmaf(dl, wprev0, v0);
                v1c = fmaf(dl, wprev1, v1c);
            }
            v0 = fmaxf(v0, 0.f); v1c = fmaxf(v1c, 0.f);
            if (i & 1) { PK(bp0[p], wprev0, v0); PK(bp1[p], wprev1, v1c); }
            else       { wprev0 = v0; wprev1 = v1c; }
        }
    }

    // Spill w to coalesced global scratch: slot-major, thread-minor.
    {
        u64* w2 = w_scratch_u64;
        #pragma unroll
        for (int p = 0; p < 32; ++p) {
            w2[(size_t)p * TOT + gt]        = bp0[p];
            w2[(size_t)(32 + p) * TOT + gt] = bp1[p];
        }
    }

    // ================= Stage 3: out = A x + B1 w + B2 u + bx =================
    u64 oa0[32], oa1[32];
    {
        const u64* bxp = (const u64*)sbx;
        #pragma unroll
        for (int p = 0; p < 32; ++p) { u64 b = bxp[p]; oa0[p] = b; oa1[p] = b; }
    }
    stream_sec<NXC/4>(oa0, oa1, sAt, x + r0*NXC, x + r1s*NXC);

    // w-section: multipliers from coalesced scratch (own thread's slots, L2-hot)
    {
        const u64* w2 = w_scratch_u64;
        #pragma unroll 1
        for (int s4 = 0; s4 < 16; ++s4) {
            u64 q00 = w2[(size_t)(2*s4)     * TOT + gt];
            u64 q01 = w2[(size_t)(2*s4 + 1) * TOT + gt];
            u64 q10 = w2[(size_t)(32 + 2*s4)     * TOT + gt];
            u64 q11 = w2[(size_t)(32 + 2*s4 + 1) * TOT + gt];
            float w00, w01, w02, w03, w10, w11, w12, w13;
            UNPK(w00, w01, q00); UNPK(w02, w03, q01);
            UNPK(w10, w11, q10); UNPK(w12, w13, q11);
            const float* col = sB1t + 4*s4*PAD;
            u64 m0, m1;
            DUP(m0, w00); DUP(m1, w10); acc_col(oa0, oa1, col,         m0, m1);
            DUP(m0, w01); DUP(m1, w11); acc_col(oa0, oa1, col + PAD,   m0, m1);
            DUP(m0, w02); DUP(m1, w12); acc_col(oa0, oa1, col + 2*PAD, m0, m1);
            DUP(m0, w03); DUP(m1, w13); acc_col(oa0, oa1, col + 3*PAD, m0, m1);
        }
    }
    stream_sec<NUC/4>(oa0, oa1, sB2t, u + r0*NUC, u + r1s*NUC);

    {
        ulonglong2* o0 = (ulonglong2*)(out + r0 * NXC);
        ulonglong2* o1 = (ulonglong2*)(out + r1 * NXC);
        #pragma unroll
        for (int q = 0; q < 16; ++q) {
            ulonglong2 t2;
            t2.x = oa0[2*q]; t2.y = oa0[2*q+1]; o0[q] = t2;
            if (v1) { t2.x = oa1[2*q]; t2.y = oa1[2*q+1]; o1[q] = t2; }
        }
    }
}

extern "C" void kernel_launch(void* const* d_in, const int* in_sizes, int n_in,
                              void* d_out, int out_size) {
    const float* x   = (const float*)d_in[0];
    const float* u   = (const float*)d_in[1];
    const float* A   = (const float*)d_in[2];
    const float* B1  = (const float*)d_in[3];
    const float* B2  = (const float*)d_in[4];
    const float* C1  = (const float*)d_in[5];
    const float* D11 = (const float*)d_in[6];
    const float* D12 = (const float*)d_in[7];
    const float* bv  = (const float*)d_in[8];
    const float* bx  = (const float*)d_in[9];
    float* out = (float*)d_out;

    const int n = in_sizes[0] / NXC;   // 262144 rows
    cudaFuncSetAttribute(ren_fused_kernel,
                         cudaFuncAttributeMaxDynamicSharedMemorySize, SMEM_BYTES);
    const int blocks = (n + RPC - 1) / RPC;
    ren_fused_kernel<<<blocks, TPB, SMEM_BYTES>>>(x, u, A, B1, B2, C1, D11, D12,
                                                  bv, bx, out, n);
}